// round 12
// baseline (speedup 1.0000x reference)
#include <cuda_runtime.h>
#include <cuda_fp16.h>
#include <cstdint>

#define NMAX 100000
#define EMAX 1600000

// ---------------- device scratch (no allocations allowed) ----------------
// g_deg is SELF-CLEANING: degcount builds it up, bin drains it back to zero.
__device__ int    g_deg[NMAX];
__device__ int    g_rowptr[NMAX + 1];
__device__ int    g_part[128];
__device__ float  g_deginv[NMAX];
__device__ unsigned char g_flag[NMAX];           // 0 none, 1 keep, 2 low (replay-invariant)
__device__ int    g_esrc[EMAX];                  // src ids binned by dst (CSR)
__device__ __half g_X1s[(size_t)NMAX * 128];     // X@W1_self + b1
__device__ __half g_X1n[(size_t)NMAX * 128];     // X@W1_neigh
__device__ __half g_h1 [(size_t)NMAX * 128];     // relu layer-1 output
__device__ __half g_Ys [(size_t)NMAX * 64];      // h1@W2_self + b2
__device__ __half g_Yn [(size_t)NMAX * 64];      // h1@W2_neigh
__device__ __half g_W1T[256 * 128];              // [n][k] cat(W1_self,W1_neigh)^T
__device__ __half g_W2T[128 * 128];              // [n][k] cat(W2_self,W2_neigh)^T
__device__ float  g_b1 [256];                    // cat(b1, 0)
__device__ float  g_b2 [128];                    // cat(b2, 0)

#define WPREP_T (256 * 128 + 128 * 128)          // 49152 weight-prep threads

// ---------------- merged: weights prep + flags + keep-row embedding copy ----------------
__global__ void k_prep(const float* __restrict__ W1s, const float* __restrict__ W1n,
                       const float* __restrict__ b1,
                       const float* __restrict__ W2s, const float* __restrict__ W2n,
                       const float* __restrict__ b2,
                       const float* __restrict__ emb, float* __restrict__ out,
                       const int* __restrict__ keep, int nk,
                       const int* __restrict__ low, int nl) {
    int i = blockIdx.x * blockDim.x + threadIdx.x;
    if (i < WPREP_T) {
        if (i < 256 * 128) {                    // W1T[n][k]
            int n = i >> 7, k = i & 127;
            float v = (n < 128) ? W1s[k * 128 + n] : W1n[k * 128 + (n - 128)];
            g_W1T[i] = __float2half(v);
        } else {                                // W2T[n][k]
            int i2 = i - 256 * 128;
            int n = i2 >> 7, k = i2 & 127;
            float v = (n < 64) ? W2s[k * 64 + n] : W2n[k * 64 + (n - 64)];
            g_W2T[i2] = __float2half(v);
        }
        if (i < 256) g_b1[i] = (i < 128) ? b1[i] : 0.f;
        if (i < 128) g_b2[i] = (i < 64) ? b2[i] : 0.f;
        return;
    }
    int j = i - WPREP_T;
    int nkt = nk * 32;
    if (j < nkt) {
        int r = j >> 5, lane = j & 31;
        int row = keep[r];
        if (lane == 0) g_flag[row] = 1;
        float2 e = *(const float2*)&emb[(size_t)row * 64 + lane * 2];
        *(float2*)&out[(size_t)row * 64 + lane * 2] = e;
    } else {
        int q = j - nkt;
        if (q < nl) g_flag[low[q]] = 2;
    }
}

__global__ void k_degcount(const int* __restrict__ dst, int E) {
    int i = blockIdx.x * blockDim.x + threadIdx.x;
    int base = i * 4;
    if (base + 3 < E) {
        int4 d = *(const int4*)&dst[base];
        atomicAdd(&g_deg[d.x], 1); atomicAdd(&g_deg[d.y], 1);
        atomicAdd(&g_deg[d.z], 1); atomicAdd(&g_deg[d.w], 1);
    } else {
        for (int j = base; j < E; j++) atomicAdd(&g_deg[dst[j]], 1);
    }
}

// ---------------- parallel exclusive scan over degrees (2 kernels) ----------------
__global__ void k_scanA(int N) {
    int i = blockIdx.x * 1024 + threadIdx.x;
    int v = (i < N) ? g_deg[i] : 0;
    #pragma unroll
    for (int o = 16; o; o >>= 1) v += __shfl_down_sync(0xffffffffu, v, o);
    __shared__ int ws[32];
    if ((threadIdx.x & 31) == 0) ws[threadIdx.x >> 5] = v;
    __syncthreads();
    if (threadIdx.x < 32) {
        int s = ws[threadIdx.x];
        #pragma unroll
        for (int o = 16; o; o >>= 1) s += __shfl_down_sync(0xffffffffu, s, o);
        if (threadIdx.x == 0) g_part[blockIdx.x] = s;   // block SUM
    }
}

__global__ void k_scanC(int N, int E) {
    int i = blockIdx.x * 1024 + threadIdx.x;
    int d = (i < N) ? g_deg[i] : 0;
    int lane = threadIdx.x & 31, w = threadIdx.x >> 5;
    int x = d;
    #pragma unroll
    for (int o = 1; o < 32; o <<= 1) {
        int y = __shfl_up_sync(0xffffffffu, x, o);
        if (lane >= o) x += y;
    }
    __shared__ int ws[32];
    __shared__ int s_pref;
    if (lane == 31) ws[w] = x;
    __syncthreads();
    if (w == 0) {
        int s = ws[lane];
        #pragma unroll
        for (int o = 1; o < 32; o <<= 1) {
            int y = __shfl_up_sync(0xffffffffu, s, o);
            if (lane >= o) s += y;
        }
        ws[lane] = s;
    } else if (w == 1) {
        int p = 0;
        for (int j = lane; j < blockIdx.x; j += 32) p += g_part[j];
        #pragma unroll
        for (int o = 16; o; o >>= 1) p += __shfl_down_sync(0xffffffffu, p, o);
        if (lane == 0) s_pref = p;
    }
    __syncthreads();
    int excl = x - d + (w ? ws[w - 1] : 0) + s_pref;
    if (i < N) {
        g_rowptr[i] = excl;
        g_deginv[i] = 1.0f / (float)((d > 1) ? d : 1);
    }
    if (blockIdx.x == 0 && threadIdx.x == 0) g_rowptr[N] = E;
}

// bin: DRAINS g_deg back to zero (self-cleaning)
__global__ void k_bin(const int* __restrict__ src, const int* __restrict__ dst, int E) {
    int i = blockIdx.x * blockDim.x + threadIdx.x;
    int base = i * 4;
    if (base + 3 < E) {
        int4 s = *(const int4*)&src[base];
        int4 d = *(const int4*)&dst[base];
        g_esrc[g_rowptr[d.x] + atomicAdd(&g_deg[d.x], -1) - 1] = s.x;
        g_esrc[g_rowptr[d.y] + atomicAdd(&g_deg[d.y], -1) - 1] = s.y;
        g_esrc[g_rowptr[d.z] + atomicAdd(&g_deg[d.z], -1) - 1] = s.z;
        g_esrc[g_rowptr[d.w] + atomicAdd(&g_deg[d.w], -1) - 1] = s.w;
    } else {
        for (int j = base; j < E; j++) {
            int d = dst[j];
            g_esrc[g_rowptr[d] + atomicAdd(&g_deg[d], -1) - 1] = src[j];
        }
    }
}

// ---------------- fp16 tensor-core GEMM (m16n8k16, ldmatrix fragments) ----------------
#define AS2 136   // 128 + 8 halves pad; row stride 272B -> ldmatrix conflict-free
#define BS2 136

#define LDSM_X4(r0, r1, r2, r3, addr) \
    asm volatile("ldmatrix.sync.aligned.m8n8.x4.shared.b16 {%0,%1,%2,%3}, [%4];" \
                 : "=r"(r0), "=r"(r1), "=r"(r2), "=r"(r3) : "r"(addr))

template <int NCOLS, bool A_F32>
__global__ void __launch_bounds__(128) k_gemm_h(const float* __restrict__ Xf, int M) {
    __shared__ __half As[64 * AS2];
    __shared__ __half Bs[64 * BS2];
    const __half* WT   = (NCOLS == 256) ? g_W1T : g_W2T;
    const float*  bias = (NCOLS == 256) ? g_b1 : g_b2;

    int bm = blockIdx.x * 64;
    int tid = threadIdx.x;
    int wid = tid >> 5, lane = tid & 31;
    int g = lane >> 2, t = lane & 3;
    int wm = wid >> 1, wn = wid & 1;

    uint32_t a_smem = (uint32_t)__cvta_generic_to_shared(As);
    uint32_t b_smem = (uint32_t)__cvta_generic_to_shared(Bs);
    int l7 = lane & 7;
    int a_row_off = ((lane >> 3) & 1) * 8;
    int a_k_off   = ((lane >> 4) & 1) * 8;
    int b_n_off   = ((lane >> 4) & 1) * 8;
    int b_k_off   = ((lane >> 3) & 1) * 8;

    if (A_F32) {
        #pragma unroll
        for (int i = 0; i < 16; i++) {
            int idx = tid + i * 128;
            int r = idx >> 5, c4 = (idx & 31) << 2;
            int row = bm + r;
            float4 v = (row < M) ? *(const float4*)&Xf[(size_t)row * 128 + c4]
                                 : make_float4(0.f, 0.f, 0.f, 0.f);
            __half2 h0 = __floats2half2_rn(v.x, v.y);
            __half2 h1 = __floats2half2_rn(v.z, v.w);
            uint2 u = make_uint2(*(uint32_t*)&h0, *(uint32_t*)&h1);
            *(uint2*)&As[r * AS2 + c4] = u;
        }
    } else {
        #pragma unroll
        for (int i = 0; i < 16; i++) {
            int idx = tid + i * 128;
            int r = idx >> 5, c4 = (idx & 31) << 2;
            int row = bm + r;
            uint2 u = (row < M) ? *(const uint2*)&g_h1[(size_t)row * 128 + c4]
                                : make_uint2(0u, 0u);
            *(uint2*)&As[r * AS2 + c4] = u;
        }
    }

    for (int bn = 0; bn < NCOLS; bn += 64) {
        __syncthreads();
        #pragma unroll
        for (int i = 0; i < 16; i++) {
            int idx = tid + i * 128;
            int r = idx >> 5, c4 = (idx & 31) << 2;
            uint2 u = *(const uint2*)&WT[(size_t)(bn + r) * 128 + c4];
            *(uint2*)&Bs[r * BS2 + c4] = u;
        }
        __syncthreads();

        float c[2][4][4];
        #pragma unroll
        for (int mt = 0; mt < 2; mt++)
            #pragma unroll
            for (int nt = 0; nt < 4; nt++)
                #pragma unroll
                for (int q = 0; q < 4; q++) c[mt][nt][q] = 0.f;

        #pragma unroll
        for (int k0 = 0; k0 < 128; k0 += 16) {
            uint32_t a[2][4];
            #pragma unroll
            for (int mt = 0; mt < 2; mt++) {
                int arow = wm * 32 + mt * 16 + l7 + a_row_off;
                uint32_t addr = a_smem + (uint32_t)((arow * AS2 + k0 + a_k_off) * 2);
                LDSM_X4(a[mt][0], a[mt][1], a[mt][2], a[mt][3], addr);
            }
            uint32_t b[4][2];
            #pragma unroll
            for (int p = 0; p < 2; p++) {
                int nrow = wn * 32 + p * 16 + l7 + b_n_off;
                uint32_t addr = b_smem + (uint32_t)((nrow * BS2 + k0 + b_k_off) * 2);
                LDSM_X4(b[2 * p][0], b[2 * p][1], b[2 * p + 1][0], b[2 * p + 1][1], addr);
            }
            #pragma unroll
            for (int mt = 0; mt < 2; mt++)
                #pragma unroll
                for (int nt = 0; nt < 4; nt++) {
                    asm volatile(
                        "mma.sync.aligned.m16n8k16.row.col.f32.f16.f16.f32 "
                        "{%0,%1,%2,%3}, {%4,%5,%6,%7}, {%8,%9}, {%0,%1,%2,%3};"
                        : "+f"(c[mt][nt][0]), "+f"(c[mt][nt][1]),
                          "+f"(c[mt][nt][2]), "+f"(c[mt][nt][3])
                        : "r"(a[mt][0]), "r"(a[mt][1]), "r"(a[mt][2]), "r"(a[mt][3]),
                          "r"(b[nt][0]), "r"(b[nt][1]));
                }
        }

        const int HALF = NCOLS / 2;
        #pragma unroll
        for (int mt = 0; mt < 2; mt++) {
            int row = bm + wm * 32 + mt * 16 + g;
            #pragma unroll
            for (int nt = 0; nt < 4; nt++) {
                int col = bn + wn * 32 + nt * 8 + 2 * t;
                float bx = bias[col], by = bias[col + 1];
                __half2 o0 = __floats2half2_rn(c[mt][nt][0] + bx, c[mt][nt][1] + by);
                __half2 o1 = __floats2half2_rn(c[mt][nt][2] + bx, c[mt][nt][3] + by);
                __half* dstS = (NCOLS == 256) ? g_X1s : g_Ys;
                __half* dstN = (NCOLS == 256) ? g_X1n : g_Yn;
                if (col < HALF) {
                    if (row < M)     *(__half2*)&dstS[(size_t)row * HALF + col] = o0;
                    if (row + 8 < M) *(__half2*)&dstS[(size_t)(row + 8) * HALF + col] = o1;
                } else {
                    int cn = col - HALF;
                    if (row < M)     *(__half2*)&dstN[(size_t)row * HALF + cn] = o0;
                    if (row + 8 < M) *(__half2*)&dstN[(size_t)(row + 8) * HALF + cn] = o1;
                }
            }
        }
    }
}

// ---------------- layer-1 aggregation: warp per node, MLP-8 fp16 gather ----------------
__global__ void k_agg1(int N) {
    int w = (blockIdx.x * blockDim.x + threadIdx.x) >> 5;
    int lane = threadIdx.x & 31;
    if (w >= N) return;
    int beg = g_rowptr[w], end = g_rowptr[w + 1];
    const uint2* Xn = (const uint2*)g_X1n;
    float ax = 0.f, ay = 0.f, az = 0.f, aw = 0.f;
    int j = beg;
    for (; j + 7 < end; j += 8) {
        uint2 u[8];
        #pragma unroll
        for (int q = 0; q < 8; q++) u[q] = Xn[(size_t)g_esrc[j + q] * 32 + lane];
        #pragma unroll
        for (int q = 0; q < 8; q++) {
            float2 a = __half22float2(*(__half2*)&u[q].x);
            float2 b = __half22float2(*(__half2*)&u[q].y);
            ax += a.x; ay += a.y; az += b.x; aw += b.y;
        }
    }
    for (; j + 3 < end; j += 4) {
        uint2 u[4];
        #pragma unroll
        for (int q = 0; q < 4; q++) u[q] = Xn[(size_t)g_esrc[j + q] * 32 + lane];
        #pragma unroll
        for (int q = 0; q < 4; q++) {
            float2 a = __half22float2(*(__half2*)&u[q].x);
            float2 b = __half22float2(*(__half2*)&u[q].y);
            ax += a.x; ay += a.y; az += b.x; aw += b.y;
        }
    }
    for (; j < end; j++) {
        uint2 u0 = Xn[(size_t)g_esrc[j] * 32 + lane];
        float2 a0 = __half22float2(*(__half2*)&u0.x), b0 = __half22float2(*(__half2*)&u0.y);
        ax += a0.x; ay += a0.y; az += b0.x; aw += b0.y;
    }
    float di = g_deginv[w];
    uint2 us = *(const uint2*)&g_X1s[(size_t)w * 128 + lane * 4];
    float2 s01 = __half22float2(*(__half2*)&us.x);
    float2 s23 = __half22float2(*(__half2*)&us.y);
    __half2 h0 = __floats2half2_rn(fmaxf(fmaf(ax, di, s01.x), 0.f),
                                   fmaxf(fmaf(ay, di, s01.y), 0.f));
    __half2 h1 = __floats2half2_rn(fmaxf(fmaf(az, di, s23.x), 0.f),
                                   fmaxf(fmaf(aw, di, s23.y), 0.f));
    uint2 uo = make_uint2(*(uint32_t*)&h0, *(uint32_t*)&h1);
    *(uint2*)&g_h1[(size_t)w * 128 + lane * 4] = uo;
}

// ---------------- layer-2 aggregation + final (non-keep rows only), MLP-8 ----------------
__global__ void k_final(const float* __restrict__ emb, float* __restrict__ out, int N) {
    int w = (blockIdx.x * blockDim.x + threadIdx.x) >> 5;
    int lane = threadIdx.x & 31;
    if (w >= N) return;
    unsigned char f = g_flag[w];
    if (f == 1) return;                       // already written by k_prep
    int beg = g_rowptr[w], end = g_rowptr[w + 1];
    const uint32_t* Yn = (const uint32_t*)g_Yn;
    float ax = 0.f, ay = 0.f;
    int j = beg;
    for (; j + 7 < end; j += 8) {
        uint32_t u[8];
        #pragma unroll
        for (int q = 0; q < 8; q++) u[q] = Yn[(size_t)g_esrc[j + q] * 32 + lane];
        #pragma unroll
        for (int q = 0; q < 8; q++) {
            float2 v = __half22float2(*(__half2*)&u[q]);
            ax += v.x; ay += v.y;
        }
    }
    for (; j + 3 < end; j += 4) {
        uint32_t u[4];
        #pragma unroll
        for (int q = 0; q < 4; q++) u[q] = Yn[(size_t)g_esrc[j + q] * 32 + lane];
        #pragma unroll
        for (int q = 0; q < 4; q++) {
            float2 v = __half22float2(*(__half2*)&u[q]);
            ax += v.x; ay += v.y;
        }
    }
    for (; j < end; j++) {
        uint32_t u0 = Yn[(size_t)g_esrc[j] * 32 + lane];
        float2 v0 = __half22float2(*(__half2*)&u0);
        ax += v0.x; ay += v0.y;
    }
    float di = g_deginv[w];
    float2 ys = __half22float2(*(__half2*)&g_Ys[(size_t)w * 64 + lane * 2]);
    float sc = (f == 2) ? 2.f : 1.f;
    float2 o;
    o.x = (ys.x + ax * di) * sc;
    o.y = (ys.y + ay * di) * sc;
    *(float2*)&out[(size_t)w * 64 + lane * 2] = o;
}

// ---------------- launch ----------------
extern "C" void kernel_launch(void* const* d_in, const int* in_sizes, int n_in,
                              void* d_out, int out_size) {
    const float* features = (const float*)d_in[0];
    const float* W1s = (const float*)d_in[1];
    const float* W1n = (const float*)d_in[2];
    const float* b1  = (const float*)d_in[3];
    const float* W2s = (const float*)d_in[4];
    const float* W2n = (const float*)d_in[5];
    const float* b2  = (const float*)d_in[6];
    const float* emb = (const float*)d_in[7];
    const int* src   = (const int*)d_in[8];
    const int* dst   = (const int*)d_in[9];
    const int* keep  = (const int*)d_in[10];
    const int* low   = (const int*)d_in[11];

    int N  = in_sizes[0] / 128;
    int E  = in_sizes[8];
    int nk = in_sizes[10];
    int nl = in_sizes[11];
    float* out = (float*)d_out;

    static cudaStream_t s2 = nullptr;
    static cudaEvent_t ev_fork = nullptr, ev_join = nullptr;
    if (!s2) {
        cudaStreamCreateWithFlags(&s2, cudaStreamNonBlocking);
        cudaEventCreateWithFlags(&ev_fork, cudaEventDisableTiming);
        cudaEventCreateWithFlags(&ev_join, cudaEventDisableTiming);
    }

    int nb = (N + 1023) / 1024;   // scan blocks (<=128)

    // fork s2 at t=0 — CSR chain depends on NOTHING (g_deg is self-cleaning)
    cudaEventRecord(ev_fork, 0);
    cudaStreamWaitEvent(s2, ev_fork, 0);

    // s2: CSR build chain
    k_degcount<<<(E / 4 + 255) / 256, 256, 0, s2>>>(dst, E);
    k_scanA<<<nb, 1024, 0, s2>>>(N);
    k_scanC<<<nb, 1024, 0, s2>>>(N, E);
    k_bin<<<(E / 4 + 255) / 256, 256, 0, s2>>>(src, dst, E);
    cudaEventRecord(ev_join, s2);

    // stream 0: merged prep (weights + flags + keep copy), then GEMM1
    k_prep<<<(WPREP_T + nk * 32 + nl + 255) / 256, 256>>>(W1s, W1n, b1, W2s, W2n, b2,
                                                          emb, out, keep, nk, low, nl);
    k_gemm_h<256, true><<<(N + 63) / 64, 128>>>(features, N);

    // join: aggregation needs CSR + layer-1 GEMM
    cudaStreamWaitEvent(0, ev_join, 0);
    k_agg1<<<(N * 32 + 511) / 512, 512>>>(N);
    k_gemm_h<128, false><<<(N + 63) / 64, 128>>>(nullptr, N);
    k_final<<<(N * 32 + 511) / 512, 512>>>(emb, out, N);
}

// round 13
// speedup vs baseline: 1.0820x; 1.0820x over previous
#include <cuda_runtime.h>
#include <cuda_fp16.h>
#include <cstdint>

#define NMAX 100000
#define EMAX 1600000

// ---------------- device scratch (no allocations allowed) ----------------
__device__ int    g_deg[NMAX];
__device__ int    g_cursor[NMAX];
__device__ int    g_rowptr[NMAX + 1];
__device__ int    g_part[128];
__device__ float  g_deginv[NMAX];
__device__ unsigned char g_flag[NMAX];           // 0 none, 1 keep, 2 low (replay-invariant)
__device__ int    g_esrc[EMAX];                  // src ids binned by dst (CSR)
__device__ __half g_X1s[(size_t)NMAX * 128];     // X@W1_self + b1
__device__ __half g_X1n[(size_t)NMAX * 128];     // X@W1_neigh
__device__ __half g_h1 [(size_t)NMAX * 128];     // relu layer-1 output
__device__ __half g_Ys [(size_t)NMAX * 64];      // h1@W2_self + b2
__device__ __half g_Yn [(size_t)NMAX * 64];      // h1@W2_neigh
__device__ __half g_W1T[256 * 128];              // [n][k] cat(W1_self,W1_neigh)^T
__device__ __half g_W2T[128 * 128];              // [n][k] cat(W2_self,W2_neigh)^T
__device__ float  g_b1 [256];                    // cat(b1, 0)
__device__ float  g_b2 [128];                    // cat(b2, 0)

// ---------------- init: zero CSR state + build fp16 transposed weights ----------------
__global__ void k_init(const float* __restrict__ W1s, const float* __restrict__ W1n,
                       const float* __restrict__ b1,
                       const float* __restrict__ W2s, const float* __restrict__ W2n,
                       const float* __restrict__ b2, int N) {
    int i = blockIdx.x * blockDim.x + threadIdx.x;
    if (i < N) { g_deg[i] = 0; g_cursor[i] = 0; }
    if (i < 256 * 128) {                        // W1T[n][k]
        int n = i >> 7, k = i & 127;
        float v = (n < 128) ? W1s[k * 128 + n] : W1n[k * 128 + (n - 128)];
        g_W1T[i] = __float2half(v);
    }
    int i2 = i - 256 * 128;
    if (i2 >= 0 && i2 < 128 * 128) {            // W2T[n][k]
        int n = i2 >> 7, k = i2 & 127;
        float v = (n < 64) ? W2s[k * 64 + n] : W2n[k * 64 + (n - 64)];
        g_W2T[i2] = __float2half(v);
    }
    if (i < 256) g_b1[i] = (i < 128) ? b1[i] : 0.f;
    if (i < 128) g_b2[i] = (i < 64) ? b2[i] : 0.f;
}

// ---------------- flags + keep-row embedding copy (merged) ----------------
__global__ void k_flagcopy(const float* __restrict__ emb, float* __restrict__ out,
                           const int* __restrict__ keep, int nk,
                           const int* __restrict__ low, int nl) {
    int i = blockIdx.x * blockDim.x + threadIdx.x;
    int nkt = nk * 32;
    if (i < nkt) {
        int r = i >> 5, lane = i & 31;
        int row = keep[r];
        if (lane == 0) g_flag[row] = 1;
        float2 e = *(const float2*)&emb[(size_t)row * 64 + lane * 2];
        *(float2*)&out[(size_t)row * 64 + lane * 2] = e;
    } else {
        int j = i - nkt;
        if (j < nl) g_flag[low[j]] = 2;
    }
}

__global__ void k_degcount(const int* __restrict__ dst, int E) {
    int i = blockIdx.x * blockDim.x + threadIdx.x;
    int base = i * 4;
    if (base + 3 < E) {
        int4 d = *(const int4*)&dst[base];
        atomicAdd(&g_deg[d.x], 1); atomicAdd(&g_deg[d.y], 1);
        atomicAdd(&g_deg[d.z], 1); atomicAdd(&g_deg[d.w], 1);
    } else {
        for (int j = base; j < E; j++) atomicAdd(&g_deg[dst[j]], 1);
    }
}

// ---------------- parallel exclusive scan over degrees (2 kernels) ----------------
__global__ void k_scanA(int N) {
    int i = blockIdx.x * 1024 + threadIdx.x;
    int v = (i < N) ? g_deg[i] : 0;
    #pragma unroll
    for (int o = 16; o; o >>= 1) v += __shfl_down_sync(0xffffffffu, v, o);
    __shared__ int ws[32];
    if ((threadIdx.x & 31) == 0) ws[threadIdx.x >> 5] = v;
    __syncthreads();
    if (threadIdx.x < 32) {
        int s = ws[threadIdx.x];
        #pragma unroll
        for (int o = 16; o; o >>= 1) s += __shfl_down_sync(0xffffffffu, s, o);
        if (threadIdx.x == 0) g_part[blockIdx.x] = s;   // block SUM
    }
}

// scanC: block-local scan + per-block reduction of g_part[0..bid)
__global__ void k_scanC(int N, int E) {
    int i = blockIdx.x * 1024 + threadIdx.x;
    int d = (i < N) ? g_deg[i] : 0;
    int lane = threadIdx.x & 31, w = threadIdx.x >> 5;
    int x = d;
    #pragma unroll
    for (int o = 1; o < 32; o <<= 1) {
        int y = __shfl_up_sync(0xffffffffu, x, o);
        if (lane >= o) x += y;
    }
    __shared__ int ws[32];
    __shared__ int s_pref;
    if (lane == 31) ws[w] = x;
    __syncthreads();
    if (w == 0) {
        int s = ws[lane];
        #pragma unroll
        for (int o = 1; o < 32; o <<= 1) {
            int y = __shfl_up_sync(0xffffffffu, s, o);
            if (lane >= o) s += y;
        }
        ws[lane] = s;
    } else if (w == 1) {
        int p = 0;
        for (int j = lane; j < blockIdx.x; j += 32) p += g_part[j];
        #pragma unroll
        for (int o = 16; o; o >>= 1) p += __shfl_down_sync(0xffffffffu, p, o);
        if (lane == 0) s_pref = p;
    }
    __syncthreads();
    int excl = x - d + (w ? ws[w - 1] : 0) + s_pref;
    if (i < N) {
        g_rowptr[i] = excl;
        g_deginv[i] = 1.0f / (float)((d > 1) ? d : 1);
    }
    if (blockIdx.x == 0 && threadIdx.x == 0) g_rowptr[N] = E;
}

__global__ void k_bin(const int* __restrict__ src, const int* __restrict__ dst, int E) {
    int i = blockIdx.x * blockDim.x + threadIdx.x;
    int base = i * 4;
    if (base + 3 < E) {
        int4 s = *(const int4*)&src[base];
        int4 d = *(const int4*)&dst[base];
        g_esrc[g_rowptr[d.x] + atomicAdd(&g_cursor[d.x], 1)] = s.x;
        g_esrc[g_rowptr[d.y] + atomicAdd(&g_cursor[d.y], 1)] = s.y;
        g_esrc[g_rowptr[d.z] + atomicAdd(&g_cursor[d.z], 1)] = s.z;
        g_esrc[g_rowptr[d.w] + atomicAdd(&g_cursor[d.w], 1)] = s.w;
    } else {
        for (int j = base; j < E; j++) {
            int d = dst[j];
            g_esrc[g_rowptr[d] + atomicAdd(&g_cursor[d], 1)] = src[j];
        }
    }
}

// ---------------- fp16 tensor-core GEMM (m16n8k16, ldmatrix fragments) ----------------
#define AS2 136   // 128 + 8 halves pad; row stride 272B -> ldmatrix conflict-free
#define BS2 136

#define LDSM_X4(r0, r1, r2, r3, addr) \
    asm volatile("ldmatrix.sync.aligned.m8n8.x4.shared.b16 {%0,%1,%2,%3}, [%4];" \
                 : "=r"(r0), "=r"(r1), "=r"(r2), "=r"(r3) : "r"(addr))

template <int NCOLS, bool A_F32>
__global__ void __launch_bounds__(128) k_gemm_h(const float* __restrict__ Xf, int M) {
    __shared__ __half As[64 * AS2];
    __shared__ __half Bs[64 * BS2];
    const __half* WT   = (NCOLS == 256) ? g_W1T : g_W2T;
    const float*  bias = (NCOLS == 256) ? g_b1 : g_b2;

    int bm = blockIdx.x * 64;
    int tid = threadIdx.x;
    int wid = tid >> 5, lane = tid & 31;
    int g = lane >> 2, t = lane & 3;
    int wm = wid >> 1, wn = wid & 1;           // 2x2 warps over 64x64

    uint32_t a_smem = (uint32_t)__cvta_generic_to_shared(As);
    uint32_t b_smem = (uint32_t)__cvta_generic_to_shared(Bs);
    // ldmatrix lane-address components
    int l7 = lane & 7;
    int a_row_off = ((lane >> 3) & 1) * 8;     // +8 rows for matrices 1,3
    int a_k_off   = ((lane >> 4) & 1) * 8;     // +8 k for matrices 2,3
    int b_n_off   = ((lane >> 4) & 1) * 8;     // +8 n for matrices 2,3
    int b_k_off   = ((lane >> 3) & 1) * 8;     // +8 k for matrices 1,3

    // stage A once (64 rows x 128 halves)
    if (A_F32) {
        #pragma unroll
        for (int i = 0; i < 16; i++) {
            int idx = tid + i * 128;
            int r = idx >> 5, c4 = (idx & 31) << 2;
            int row = bm + r;
            float4 v = (row < M) ? *(const float4*)&Xf[(size_t)row * 128 + c4]
                                 : make_float4(0.f, 0.f, 0.f, 0.f);
            __half2 h0 = __floats2half2_rn(v.x, v.y);
            __half2 h1 = __floats2half2_rn(v.z, v.w);
            uint2 u = make_uint2(*(uint32_t*)&h0, *(uint32_t*)&h1);
            *(uint2*)&As[r * AS2 + c4] = u;
        }
    } else {
        #pragma unroll
        for (int i = 0; i < 16; i++) {
            int idx = tid + i * 128;
            int r = idx >> 5, c4 = (idx & 31) << 2;
            int row = bm + r;
            uint2 u = (row < M) ? *(const uint2*)&g_h1[(size_t)row * 128 + c4]
                                : make_uint2(0u, 0u);
            *(uint2*)&As[r * AS2 + c4] = u;
        }
    }

    for (int bn = 0; bn < NCOLS; bn += 64) {
        __syncthreads();
        #pragma unroll
        for (int i = 0; i < 16; i++) {
            int idx = tid + i * 128;
            int r = idx >> 5, c4 = (idx & 31) << 2;
            uint2 u = *(const uint2*)&WT[(size_t)(bn + r) * 128 + c4];
            *(uint2*)&Bs[r * BS2 + c4] = u;
        }
        __syncthreads();

        float c[2][4][4];
        #pragma unroll
        for (int mt = 0; mt < 2; mt++)
            #pragma unroll
            for (int nt = 0; nt < 4; nt++)
                #pragma unroll
                for (int q = 0; q < 4; q++) c[mt][nt][q] = 0.f;

        #pragma unroll
        for (int k0 = 0; k0 < 128; k0 += 16) {
            uint32_t a[2][4];
            #pragma unroll
            for (int mt = 0; mt < 2; mt++) {
                int arow = wm * 32 + mt * 16 + l7 + a_row_off;
                uint32_t addr = a_smem + (uint32_t)((arow * AS2 + k0 + a_k_off) * 2);
                LDSM_X4(a[mt][0], a[mt][1], a[mt][2], a[mt][3], addr);
            }
            uint32_t b[4][2];
            #pragma unroll
            for (int p = 0; p < 2; p++) {      // nt pair {2p, 2p+1}
                int nrow = wn * 32 + p * 16 + l7 + b_n_off;
                uint32_t addr = b_smem + (uint32_t)((nrow * BS2 + k0 + b_k_off) * 2);
                LDSM_X4(b[2 * p][0], b[2 * p][1], b[2 * p + 1][0], b[2 * p + 1][1], addr);
            }
            #pragma unroll
            for (int mt = 0; mt < 2; mt++)
                #pragma unroll
                for (int nt = 0; nt < 4; nt++) {
                    asm volatile(
                        "mma.sync.aligned.m16n8k16.row.col.f32.f16.f16.f32 "
                        "{%0,%1,%2,%3}, {%4,%5,%6,%7}, {%8,%9}, {%0,%1,%2,%3};"
                        : "+f"(c[mt][nt][0]), "+f"(c[mt][nt][1]),
                          "+f"(c[mt][nt][2]), "+f"(c[mt][nt][3])
                        : "r"(a[mt][0]), "r"(a[mt][1]), "r"(a[mt][2]), "r"(a[mt][3]),
                          "r"(b[nt][0]), "r"(b[nt][1]));
                }
        }

        const int HALF = NCOLS / 2;
        #pragma unroll
        for (int mt = 0; mt < 2; mt++) {
            int row = bm + wm * 32 + mt * 16 + g;
            #pragma unroll
            for (int nt = 0; nt < 4; nt++) {
                int col = bn + wn * 32 + nt * 8 + 2 * t;
                float bx = bias[col], by = bias[col + 1];
                __half2 o0 = __floats2half2_rn(c[mt][nt][0] + bx, c[mt][nt][1] + by);
                __half2 o1 = __floats2half2_rn(c[mt][nt][2] + bx, c[mt][nt][3] + by);
                __half* dstS = (NCOLS == 256) ? g_X1s : g_Ys;
                __half* dstN = (NCOLS == 256) ? g_X1n : g_Yn;
                if (col < HALF) {
                    if (row < M)     *(__half2*)&dstS[(size_t)row * HALF + col] = o0;
                    if (row + 8 < M) *(__half2*)&dstS[(size_t)(row + 8) * HALF + col] = o1;
                } else {
                    int cn = col - HALF;
                    if (row < M)     *(__half2*)&dstN[(size_t)row * HALF + cn] = o0;
                    if (row + 8 < M) *(__half2*)&dstN[(size_t)(row + 8) * HALF + cn] = o1;
                }
            }
        }
    }
}

// ---------------- layer-1 aggregation: warp per node, fp16 gather ----------------
__global__ void k_agg1(int N) {
    int w = (blockIdx.x * blockDim.x + threadIdx.x) >> 5;
    int lane = threadIdx.x & 31;
    if (w >= N) return;
    int beg = g_rowptr[w], end = g_rowptr[w + 1];
    const uint2* Xn = (const uint2*)g_X1n;   // row = 32 uint2 (4 halves each)
    float ax = 0.f, ay = 0.f, az = 0.f, aw = 0.f;
    int j = beg;
    for (; j + 3 < end; j += 4) {
        int s0 = g_esrc[j],     s1 = g_esrc[j + 1];
        int s2 = g_esrc[j + 2], s3 = g_esrc[j + 3];
        uint2 u0 = Xn[(size_t)s0 * 32 + lane];
        uint2 u1 = Xn[(size_t)s1 * 32 + lane];
        uint2 u2 = Xn[(size_t)s2 * 32 + lane];
        uint2 u3 = Xn[(size_t)s3 * 32 + lane];
        float2 a0 = __half22float2(*(__half2*)&u0.x), b0 = __half22float2(*(__half2*)&u0.y);
        float2 a1 = __half22float2(*(__half2*)&u1.x), b1 = __half22float2(*(__half2*)&u1.y);
        float2 a2 = __half22float2(*(__half2*)&u2.x), b2 = __half22float2(*(__half2*)&u2.y);
        float2 a3 = __half22float2(*(__half2*)&u3.x), b3 = __half22float2(*(__half2*)&u3.y);
        ax += (a0.x + a1.x) + (a2.x + a3.x);
        ay += (a0.y + a1.y) + (a2.y + a3.y);
        az += (b0.x + b1.x) + (b2.x + b3.x);
        aw += (b0.y + b1.y) + (b2.y + b3.y);
    }
    for (; j < end; j++) {
        uint2 u0 = Xn[(size_t)g_esrc[j] * 32 + lane];
        float2 a0 = __half22float2(*(__half2*)&u0.x), b0 = __half22float2(*(__half2*)&u0.y);
        ax += a0.x; ay += a0.y; az += b0.x; aw += b0.y;
    }
    float di = g_deginv[w];
    uint2 us = *(const uint2*)&g_X1s[(size_t)w * 128 + lane * 4];
    float2 s01 = __half22float2(*(__half2*)&us.x);
    float2 s23 = __half22float2(*(__half2*)&us.y);
    __half2 h0 = __floats2half2_rn(fmaxf(fmaf(ax, di, s01.x), 0.f),
                                   fmaxf(fmaf(ay, di, s01.y), 0.f));
    __half2 h1 = __floats2half2_rn(fmaxf(fmaf(az, di, s23.x), 0.f),
                                   fmaxf(fmaf(aw, di, s23.y), 0.f));
    uint2 uo = make_uint2(*(uint32_t*)&h0, *(uint32_t*)&h1);
    *(uint2*)&g_h1[(size_t)w * 128 + lane * 4] = uo;
}

// ---------------- layer-2 aggregation + final (non-keep rows only) ----------------
__global__ void k_final(const float* __restrict__ emb, float* __restrict__ out, int N) {
    int w = (blockIdx.x * blockDim.x + threadIdx.x) >> 5;
    int lane = threadIdx.x & 31;
    if (w >= N) return;
    unsigned char f = g_flag[w];
    if (f == 1) return;                       // already written by k_flagcopy
    int beg = g_rowptr[w], end = g_rowptr[w + 1];
    const uint32_t* Yn = (const uint32_t*)g_Yn;  // row = 32 half2
    float ax = 0.f, ay = 0.f;
    int j = beg;
    for (; j + 3 < end; j += 4) {
        uint32_t u0 = Yn[(size_t)g_esrc[j]     * 32 + lane];
        uint32_t u1 = Yn[(size_t)g_esrc[j + 1] * 32 + lane];
        uint32_t u2 = Yn[(size_t)g_esrc[j + 2] * 32 + lane];
        uint32_t u3 = Yn[(size_t)g_esrc[j + 3] * 32 + lane];
        float2 v0 = __half22float2(*(__half2*)&u0);
        float2 v1 = __half22float2(*(__half2*)&u1);
        float2 v2 = __half22float2(*(__half2*)&u2);
        float2 v3 = __half22float2(*(__half2*)&u3);
        ax += (v0.x + v1.x) + (v2.x + v3.x);
        ay += (v0.y + v1.y) + (v2.y + v3.y);
    }
    for (; j < end; j++) {
        uint32_t u0 = Yn[(size_t)g_esrc[j] * 32 + lane];
        float2 v0 = __half22float2(*(__half2*)&u0);
        ax += v0.x; ay += v0.y;
    }
    float di = g_deginv[w];
    float2 ys = __half22float2(*(__half2*)&g_Ys[(size_t)w * 64 + lane * 2]);
    float sc = (f == 2) ? 2.f : 1.f;
    float2 o;
    o.x = (ys.x + ax * di) * sc;
    o.y = (ys.y + ay * di) * sc;
    *(float2*)&out[(size_t)w * 64 + lane * 2] = o;
}

// ---------------- launch ----------------
extern "C" void kernel_launch(void* const* d_in, const int* in_sizes, int n_in,
                              void* d_out, int out_size) {
    const float* features = (const float*)d_in[0];
    const float* W1s = (const float*)d_in[1];
    const float* W1n = (const float*)d_in[2];
    const float* b1  = (const float*)d_in[3];
    const float* W2s = (const float*)d_in[4];
    const float* W2n = (const float*)d_in[5];
    const float* b2  = (const float*)d_in[6];
    const float* emb = (const float*)d_in[7];
    const int* src   = (const int*)d_in[8];
    const int* dst   = (const int*)d_in[9];
    const int* keep  = (const int*)d_in[10];
    const int* low   = (const int*)d_in[11];

    int N  = in_sizes[0] / 128;
    int E  = in_sizes[8];
    int nk = in_sizes[10];
    int nl = in_sizes[11];
    float* out = (float*)d_out;

    static cudaStream_t s2 = nullptr;
    static cudaEvent_t ev_fork = nullptr, ev_join = nullptr;
    if (!s2) {
        cudaStreamCreateWithFlags(&s2, cudaStreamNonBlocking);
        cudaEventCreateWithFlags(&ev_fork, cudaEventDisableTiming);
        cudaEventCreateWithFlags(&ev_join, cudaEventDisableTiming);
    }

    int nb = (N + 1023) / 1024;   // scan blocks (<=128)

    // stream 0: init, then fork CSR build onto s2
    k_init<<<(N + 255) / 256, 256>>>(W1s, W1n, b1, W2s, W2n, b2, N);
    cudaEventRecord(ev_fork, 0);
    cudaStreamWaitEvent(s2, ev_fork, 0);

    // s2: CSR build chain (independent of GEMM1)
    k_degcount<<<(E / 4 + 255) / 256, 256, 0, s2>>>(dst, E);
    k_scanA<<<nb, 1024, 0, s2>>>(N);
    k_scanC<<<nb, 1024, 0, s2>>>(N, E);
    k_bin<<<(E / 4 + 255) / 256, 256, 0, s2>>>(src, dst, E);
    cudaEventRecord(ev_join, s2);

    // stream 0 meanwhile: GEMM1, flags+keepcopy
    k_gemm_h<256, true><<<(N + 63) / 64, 128>>>(features, N);
    k_flagcopy<<<(nk * 32 + nl + 255) / 256, 256>>>(emb, out, keep, nk, low, nl);

    // join: aggregation needs CSR + layer-1 GEMM
    cudaStreamWaitEvent(0, ev_join, 0);
    k_agg1<<<(N + 7) / 8, 256>>>(N);
    k_gemm_h<128, false><<<(N + 63) / 64, 128>>>(nullptr, N);
    k_final<<<(N + 7) / 8, 256>>>(emb, out, N);
}

// round 14
// speedup vs baseline: 1.1022x; 1.0187x over previous
#include <cuda_runtime.h>
#include <cuda_fp16.h>
#include <cstdint>

#define NMAX 100000
#define EMAX 1600000

// ---------------- device scratch (no allocations allowed) ----------------
__device__ int    g_deg[NMAX];
__device__ int    g_cursor[NMAX];
__device__ int    g_rowptr[NMAX + 1];
__device__ int    g_part[128];
__device__ float  g_deginv[NMAX];
__device__ unsigned char g_flag[NMAX];           // 0 none, 1 keep, 2 low (replay-invariant)
__device__ int    g_esrc[EMAX];                  // src ids binned by dst (CSR)
__device__ __half g_X1s[(size_t)NMAX * 128];     // X@W1_self + b1
__device__ __half g_X1n[(size_t)NMAX * 128];     // X@W1_neigh
__device__ __half g_h1 [(size_t)NMAX * 128];     // relu layer-1 output
__device__ __half g_Ys [(size_t)NMAX * 64];      // h1@W2_self + b2
__device__ __half g_Yn [(size_t)NMAX * 64];      // h1@W2_neigh
__device__ __half g_W1T[256 * 128];              // [n][k] cat(W1_self,W1_neigh)^T
__device__ __half g_W2T[128 * 128];              // [n][k] cat(W2_self,W2_neigh)^T
__device__ float  g_b1 [256];                    // cat(b1, 0)
__device__ float  g_b2 [128];                    // cat(b2, 0)

// ---------------- init: zero CSR state + build fp16 transposed weights ----------------
__global__ void k_init(const float* __restrict__ W1s, const float* __restrict__ W1n,
                       const float* __restrict__ b1,
                       const float* __restrict__ W2s, const float* __restrict__ W2n,
                       const float* __restrict__ b2, int N) {
    int i = blockIdx.x * blockDim.x + threadIdx.x;
    if (i < N) { g_deg[i] = 0; g_cursor[i] = 0; }
    if (i < 256 * 128) {                        // W1T[n][k]
        int n = i >> 7, k = i & 127;
        float v = (n < 128) ? W1s[k * 128 + n] : W1n[k * 128 + (n - 128)];
        g_W1T[i] = __float2half(v);
    }
    int i2 = i - 256 * 128;
    if (i2 >= 0 && i2 < 128 * 128) {            // W2T[n][k]
        int n = i2 >> 7, k = i2 & 127;
        float v = (n < 64) ? W2s[k * 64 + n] : W2n[k * 64 + (n - 64)];
        g_W2T[i2] = __float2half(v);
    }
    if (i < 256) g_b1[i] = (i < 128) ? b1[i] : 0.f;
    if (i < 128) g_b2[i] = (i < 64) ? b2[i] : 0.f;
}

// ---------------- flags + keep-row embedding copy (merged) ----------------
__global__ void k_flagcopy(const float* __restrict__ emb, float* __restrict__ out,
                           const int* __restrict__ keep, int nk,
                           const int* __restrict__ low, int nl) {
    int i = blockIdx.x * blockDim.x + threadIdx.x;
    int nkt = nk * 32;
    if (i < nkt) {
        int r = i >> 5, lane = i & 31;
        int row = keep[r];
        if (lane == 0) g_flag[row] = 1;
        float2 e = *(const float2*)&emb[(size_t)row * 64 + lane * 2];
        *(float2*)&out[(size_t)row * 64 + lane * 2] = e;
    } else {
        int j = i - nkt;
        if (j < nl) g_flag[low[j]] = 2;
    }
}

__global__ void k_degcount(const int* __restrict__ dst, int E) {
    int i = blockIdx.x * blockDim.x + threadIdx.x;
    int base = i * 4;
    if (base + 3 < E) {
        int4 d = *(const int4*)&dst[base];
        atomicAdd(&g_deg[d.x], 1); atomicAdd(&g_deg[d.y], 1);
        atomicAdd(&g_deg[d.z], 1); atomicAdd(&g_deg[d.w], 1);
    } else {
        for (int j = base; j < E; j++) atomicAdd(&g_deg[dst[j]], 1);
    }
}

// ---------------- parallel exclusive scan over degrees (2 kernels) ----------------
__global__ void k_scanA(int N) {
    int i = blockIdx.x * 1024 + threadIdx.x;
    int v = (i < N) ? g_deg[i] : 0;
    #pragma unroll
    for (int o = 16; o; o >>= 1) v += __shfl_down_sync(0xffffffffu, v, o);
    __shared__ int ws[32];
    if ((threadIdx.x & 31) == 0) ws[threadIdx.x >> 5] = v;
    __syncthreads();
    if (threadIdx.x < 32) {
        int s = ws[threadIdx.x];
        #pragma unroll
        for (int o = 16; o; o >>= 1) s += __shfl_down_sync(0xffffffffu, s, o);
        if (threadIdx.x == 0) g_part[blockIdx.x] = s;   // block SUM
    }
}

// scanC: block-local scan + per-block reduction of g_part[0..bid)
__global__ void k_scanC(int N, int E) {
    int i = blockIdx.x * 1024 + threadIdx.x;
    int d = (i < N) ? g_deg[i] : 0;
    int lane = threadIdx.x & 31, w = threadIdx.x >> 5;
    int x = d;
    #pragma unroll
    for (int o = 1; o < 32; o <<= 1) {
        int y = __shfl_up_sync(0xffffffffu, x, o);
        if (lane >= o) x += y;
    }
    __shared__ int ws[32];
    __shared__ int s_pref;
    if (lane == 31) ws[w] = x;
    __syncthreads();
    if (w == 0) {
        int s = ws[lane];
        #pragma unroll
        for (int o = 1; o < 32; o <<= 1) {
            int y = __shfl_up_sync(0xffffffffu, s, o);
            if (lane >= o) s += y;
        }
        ws[lane] = s;
    } else if (w == 1) {
        int p = 0;
        for (int j = lane; j < blockIdx.x; j += 32) p += g_part[j];
        #pragma unroll
        for (int o = 16; o; o >>= 1) p += __shfl_down_sync(0xffffffffu, p, o);
        if (lane == 0) s_pref = p;
    }
    __syncthreads();
    int excl = x - d + (w ? ws[w - 1] : 0) + s_pref;
    if (i < N) {
        g_rowptr[i] = excl;
        g_deginv[i] = 1.0f / (float)((d > 1) ? d : 1);
    }
    if (blockIdx.x == 0 && threadIdx.x == 0) g_rowptr[N] = E;
}

__global__ void k_bin(const int* __restrict__ src, const int* __restrict__ dst, int E) {
    int i = blockIdx.x * blockDim.x + threadIdx.x;
    int base = i * 4;
    if (base + 3 < E) {
        int4 s = *(const int4*)&src[base];
        int4 d = *(const int4*)&dst[base];
        g_esrc[g_rowptr[d.x] + atomicAdd(&g_cursor[d.x], 1)] = s.x;
        g_esrc[g_rowptr[d.y] + atomicAdd(&g_cursor[d.y], 1)] = s.y;
        g_esrc[g_rowptr[d.z] + atomicAdd(&g_cursor[d.z], 1)] = s.z;
        g_esrc[g_rowptr[d.w] + atomicAdd(&g_cursor[d.w], 1)] = s.w;
    } else {
        for (int j = base; j < E; j++) {
            int d = dst[j];
            g_esrc[g_rowptr[d] + atomicAdd(&g_cursor[d], 1)] = src[j];
        }
    }
}

// ---------------- fp16 tensor-core GEMM (m16n8k16, ldmatrix fragments) ----------------
#define AS2 136   // 128 + 8 halves pad; row stride 272B -> ldmatrix conflict-free
#define BS2 136

#define LDSM_X4(r0, r1, r2, r3, addr) \
    asm volatile("ldmatrix.sync.aligned.m8n8.x4.shared.b16 {%0,%1,%2,%3}, [%4];" \
                 : "=r"(r0), "=r"(r1), "=r"(r2), "=r"(r3) : "r"(addr))

template <int NCOLS, bool A_F32>
__global__ void __launch_bounds__(128) k_gemm_h(const float* __restrict__ Xf, int M) {
    __shared__ __half As[64 * AS2];
    __shared__ __half Bs[64 * BS2];
    const __half* WT   = (NCOLS == 256) ? g_W1T : g_W2T;
    const float*  bias = (NCOLS == 256) ? g_b1 : g_b2;

    int bm = blockIdx.x * 64;
    int tid = threadIdx.x;
    int wid = tid >> 5, lane = tid & 31;
    int g = lane >> 2, t = lane & 3;
    int wm = wid >> 1, wn = wid & 1;           // 2x2 warps over 64x64

    uint32_t a_smem = (uint32_t)__cvta_generic_to_shared(As);
    uint32_t b_smem = (uint32_t)__cvta_generic_to_shared(Bs);
    int l7 = lane & 7;
    int a_row_off = ((lane >> 3) & 1) * 8;
    int a_k_off   = ((lane >> 4) & 1) * 8;
    int b_n_off   = ((lane >> 4) & 1) * 8;
    int b_k_off   = ((lane >> 3) & 1) * 8;

    // stage A once (64 rows x 128 halves)
    if (A_F32) {
        #pragma unroll
        for (int i = 0; i < 16; i++) {
            int idx = tid + i * 128;
            int r = idx >> 5, c4 = (idx & 31) << 2;
            int row = bm + r;
            float4 v = (row < M) ? *(const float4*)&Xf[(size_t)row * 128 + c4]
                                 : make_float4(0.f, 0.f, 0.f, 0.f);
            __half2 h0 = __floats2half2_rn(v.x, v.y);
            __half2 h1 = __floats2half2_rn(v.z, v.w);
            uint2 u = make_uint2(*(uint32_t*)&h0, *(uint32_t*)&h1);
            *(uint2*)&As[r * AS2 + c4] = u;
        }
    } else {
        #pragma unroll
        for (int i = 0; i < 16; i++) {
            int idx = tid + i * 128;
            int r = idx >> 5, c4 = (idx & 31) << 2;
            int row = bm + r;
            uint2 u = (row < M) ? *(const uint2*)&g_h1[(size_t)row * 128 + c4]
                                : make_uint2(0u, 0u);
            *(uint2*)&As[r * AS2 + c4] = u;
        }
    }

    for (int bn = 0; bn < NCOLS; bn += 64) {
        __syncthreads();
        #pragma unroll
        for (int i = 0; i < 16; i++) {
            int idx = tid + i * 128;
            int r = idx >> 5, c4 = (idx & 31) << 2;
            uint2 u = *(const uint2*)&WT[(size_t)(bn + r) * 128 + c4];
            *(uint2*)&Bs[r * BS2 + c4] = u;
        }
        __syncthreads();

        float c[2][4][4];
        #pragma unroll
        for (int mt = 0; mt < 2; mt++)
            #pragma unroll
            for (int nt = 0; nt < 4; nt++)
                #pragma unroll
                for (int q = 0; q < 4; q++) c[mt][nt][q] = 0.f;

        #pragma unroll
        for (int k0 = 0; k0 < 128; k0 += 16) {
            uint32_t a[2][4];
            #pragma unroll
            for (int mt = 0; mt < 2; mt++) {
                int arow = wm * 32 + mt * 16 + l7 + a_row_off;
                uint32_t addr = a_smem + (uint32_t)((arow * AS2 + k0 + a_k_off) * 2);
                LDSM_X4(a[mt][0], a[mt][1], a[mt][2], a[mt][3], addr);
            }
            uint32_t b[4][2];
            #pragma unroll
            for (int p = 0; p < 2; p++) {
                int nrow = wn * 32 + p * 16 + l7 + b_n_off;
                uint32_t addr = b_smem + (uint32_t)((nrow * BS2 + k0 + b_k_off) * 2);
                LDSM_X4(b[2 * p][0], b[2 * p][1], b[2 * p + 1][0], b[2 * p + 1][1], addr);
            }
            #pragma unroll
            for (int mt = 0; mt < 2; mt++)
                #pragma unroll
                for (int nt = 0; nt < 4; nt++) {
                    asm volatile(
                        "mma.sync.aligned.m16n8k16.row.col.f32.f16.f16.f32 "
                        "{%0,%1,%2,%3}, {%4,%5,%6,%7}, {%8,%9}, {%0,%1,%2,%3};"
                        : "+f"(c[mt][nt][0]), "+f"(c[mt][nt][1]),
                          "+f"(c[mt][nt][2]), "+f"(c[mt][nt][3])
                        : "r"(a[mt][0]), "r"(a[mt][1]), "r"(a[mt][2]), "r"(a[mt][3]),
                          "r"(b[nt][0]), "r"(b[nt][1]));
                }
        }

        const int HALF = NCOLS / 2;
        #pragma unroll
        for (int mt = 0; mt < 2; mt++) {
            int row = bm + wm * 32 + mt * 16 + g;
            #pragma unroll
            for (int nt = 0; nt < 4; nt++) {
                int col = bn + wn * 32 + nt * 8 + 2 * t;
                float bx = bias[col], by = bias[col + 1];
                __half2 o0 = __floats2half2_rn(c[mt][nt][0] + bx, c[mt][nt][1] + by);
                __half2 o1 = __floats2half2_rn(c[mt][nt][2] + bx, c[mt][nt][3] + by);
                __half* dstS = (NCOLS == 256) ? g_X1s : g_Ys;
                __half* dstN = (NCOLS == 256) ? g_X1n : g_Yn;
                if (col < HALF) {
                    if (row < M)     *(__half2*)&dstS[(size_t)row * HALF + col] = o0;
                    if (row + 8 < M) *(__half2*)&dstS[(size_t)(row + 8) * HALF + col] = o1;
                } else {
                    int cn = col - HALF;
                    if (row < M)     *(__half2*)&dstN[(size_t)row * HALF + cn] = o0;
                    if (row + 8 < M) *(__half2*)&dstN[(size_t)(row + 8) * HALF + cn] = o1;
                }
            }
        }
    }
}

// ---------------- layer-1 aggregation: warp per node, 2 edges/warp (uint4) ----------------
// Lanes 0-15 handle even edges, lanes 16-31 odd edges; each lane covers 8 channels
// (uint4 = 16B). Halves merged at the end with one shfl_xor(16) per accumulator.
__global__ void k_agg1(int N) {
    int w = (blockIdx.x * blockDim.x + threadIdx.x) >> 5;
    int lane = threadIdx.x & 31;
    if (w >= N) return;
    int half = lane >> 4;        // 0 or 1
    int hl   = lane & 15;        // channel group: halves [hl*8, hl*8+8)
    int beg = g_rowptr[w], end = g_rowptr[w + 1];
    const uint4* Xn = (const uint4*)g_X1n;   // row = 16 uint4

    float acc[8];
    #pragma unroll
    for (int q = 0; q < 8; q++) acc[q] = 0.f;

    int j = beg + half;
    for (; j + 6 < end; j += 8) {            // 4 edges per half per iter
        int s0 = g_esrc[j],     s1 = g_esrc[j + 2];
        int s2 = g_esrc[j + 4], s3 = g_esrc[j + 6];
        uint4 u0 = Xn[(size_t)s0 * 16 + hl];
        uint4 u1 = Xn[(size_t)s1 * 16 + hl];
        uint4 u2 = Xn[(size_t)s2 * 16 + hl];
        uint4 u3 = Xn[(size_t)s3 * 16 + hl];
        const uint32_t* uu[4] = {&u0.x, &u1.x, &u2.x, &u3.x};
        #pragma unroll
        for (int e = 0; e < 4; e++) {
            #pragma unroll
            for (int q = 0; q < 4; q++) {
                float2 v = __half22float2(*(const __half2*)&uu[e][q]);
                acc[2 * q]     += v.x;
                acc[2 * q + 1] += v.y;
            }
        }
    }
    for (; j < end; j += 2) {
        uint4 u0 = Xn[(size_t)g_esrc[j] * 16 + hl];
        const uint32_t* uu = &u0.x;
        #pragma unroll
        for (int q = 0; q < 4; q++) {
            float2 v = __half22float2(*(const __half2*)&uu[q]);
            acc[2 * q]     += v.x;
            acc[2 * q + 1] += v.y;
        }
    }
    // merge even/odd halves
    #pragma unroll
    for (int q = 0; q < 8; q++) acc[q] += __shfl_xor_sync(0xffffffffu, acc[q], 16);

    if (half == 0) {
        float di = g_deginv[w];
        uint4 us = *(const uint4*)&g_X1s[(size_t)w * 128 + hl * 8];
        const uint32_t* su = &us.x;
        uint4 uo;
        uint32_t* ou = &uo.x;
        #pragma unroll
        for (int q = 0; q < 4; q++) {
            float2 s = __half22float2(*(const __half2*)&su[q]);
            float hx = fmaxf(fmaf(acc[2 * q],     di, s.x), 0.f);
            float hy = fmaxf(fmaf(acc[2 * q + 1], di, s.y), 0.f);
            __half2 h = __floats2half2_rn(hx, hy);
            ou[q] = *(uint32_t*)&h;
        }
        *(uint4*)&g_h1[(size_t)w * 128 + hl * 8] = uo;
    }
}

// ---------------- layer-2 aggregation + final (non-keep rows only) ----------------
__global__ void k_final(const float* __restrict__ emb, float* __restrict__ out, int N) {
    int w = (blockIdx.x * blockDim.x + threadIdx.x) >> 5;
    int lane = threadIdx.x & 31;
    if (w >= N) return;
    unsigned char f = g_flag[w];
    if (f == 1) return;                       // already written by k_flagcopy
    int beg = g_rowptr[w], end = g_rowptr[w + 1];
    const uint32_t* Yn = (const uint32_t*)g_Yn;  // row = 32 half2
    float ax = 0.f, ay = 0.f;
    int j = beg;
    for (; j + 3 < end; j += 4) {
        uint32_t u0 = Yn[(size_t)g_esrc[j]     * 32 + lane];
        uint32_t u1 = Yn[(size_t)g_esrc[j + 1] * 32 + lane];
        uint32_t u2 = Yn[(size_t)g_esrc[j + 2] * 32 + lane];
        uint32_t u3 = Yn[(size_t)g_esrc[j + 3] * 32 + lane];
        float2 v0 = __half22float2(*(__half2*)&u0);
        float2 v1 = __half22float2(*(__half2*)&u1);
        float2 v2 = __half22float2(*(__half2*)&u2);
        float2 v3 = __half22float2(*(__half2*)&u3);
        ax += (v0.x + v1.x) + (v2.x + v3.x);
        ay += (v0.y + v1.y) + (v2.y + v3.y);
    }
    for (; j < end; j++) {
        uint32_t u0 = Yn[(size_t)g_esrc[j] * 32 + lane];
        float2 v0 = __half22float2(*(__half2*)&u0);
        ax += v0.x; ay += v0.y;
    }
    float di = g_deginv[w];
    float2 ys = __half22float2(*(__half2*)&g_Ys[(size_t)w * 64 + lane * 2]);
    float sc = (f == 2) ? 2.f : 1.f;
    float2 o;
    o.x = (ys.x + ax * di) * sc;
    o.y = (ys.y + ay * di) * sc;
    *(float2*)&out[(size_t)w * 64 + lane * 2] = o;
}

// ---------------- launch ----------------
extern "C" void kernel_launch(void* const* d_in, const int* in_sizes, int n_in,
                              void* d_out, int out_size) {
    const float* features = (const float*)d_in[0];
    const float* W1s = (const float*)d_in[1];
    const float* W1n = (const float*)d_in[2];
    const float* b1  = (const float*)d_in[3];
    const float* W2s = (const float*)d_in[4];
    const float* W2n = (const float*)d_in[5];
    const float* b2  = (const float*)d_in[6];
    const float* emb = (const float*)d_in[7];
    const int* src   = (const int*)d_in[8];
    const int* dst   = (const int*)d_in[9];
    const int* keep  = (const int*)d_in[10];
    const int* low   = (const int*)d_in[11];

    int N  = in_sizes[0] / 128;
    int E  = in_sizes[8];
    int nk = in_sizes[10];
    int nl = in_sizes[11];
    float* out = (float*)d_out;

    static cudaStream_t s2 = nullptr;
    static cudaEvent_t ev_fork = nullptr, ev_join = nullptr;
    if (!s2) {
        cudaStreamCreateWithFlags(&s2, cudaStreamNonBlocking);
        cudaEventCreateWithFlags(&ev_fork, cudaEventDisableTiming);
        cudaEventCreateWithFlags(&ev_join, cudaEventDisableTiming);
    }

    int nb = (N + 1023) / 1024;   // scan blocks (<=128)

    // stream 0: init, then fork CSR build onto s2
    k_init<<<(N + 255) / 256, 256>>>(W1s, W1n, b1, W2s, W2n, b2, N);
    cudaEventRecord(ev_fork, 0);
    cudaStreamWaitEvent(s2, ev_fork, 0);

    // s2: CSR build chain (independent of GEMM1)
    k_degcount<<<(E / 4 + 255) / 256, 256, 0, s2>>>(dst, E);
    k_scanA<<<nb, 1024, 0, s2>>>(N);
    k_scanC<<<nb, 1024, 0, s2>>>(N, E);
    k_bin<<<(E / 4 + 255) / 256, 256, 0, s2>>>(src, dst, E);
    cudaEventRecord(ev_join, s2);

    // stream 0 meanwhile: GEMM1, flags+keepcopy
    k_gemm_h<256, true><<<(N + 63) / 64, 128>>>(features, N);
    k_flagcopy<<<(nk * 32 + nl + 255) / 256, 256>>>(emb, out, keep, nk, low, nl);

    // join: aggregation needs CSR + layer-1 GEMM
    cudaStreamWaitEvent(0, ev_join, 0);
    k_agg1<<<(N + 7) / 8, 256>>>(N);
    k_gemm_h<128, false><<<(N + 63) / 64, 128>>>(nullptr, N);
    k_final<<<(N + 7) / 8, 256>>>(emb, out, N);
}

// round 16
// speedup vs baseline: 1.1130x; 1.0098x over previous
#include <cuda_runtime.h>
#include <cuda_fp16.h>
#include <cstdint>

#define NMAX 100000
#define EMAX 1600000

// ---------------- device scratch (no allocations allowed) ----------------
__device__ int    g_deg[NMAX];
__device__ int    g_cursor[NMAX];
__device__ int    g_rowptr[NMAX + 1];
__device__ int    g_part[128];
__device__ float  g_deginv[NMAX];
__device__ unsigned char g_flag[NMAX];           // 0 none, 1 keep, 2 low (replay-invariant)
__device__ int    g_esrc[EMAX];                  // src ids binned by dst (CSR)
__device__ __half g_X1s[(size_t)NMAX * 128];     // X@W1_self + b1
__device__ __half g_X1n[(size_t)NMAX * 128];     // X@W1_neigh
__device__ __half g_h1 [(size_t)NMAX * 128];     // relu layer-1 output
__device__ __half g_Ys [(size_t)NMAX * 64];      // h1@W2_self + b2
__device__ __half g_Yn [(size_t)NMAX * 64];      // h1@W2_neigh
__device__ __half g_W1T[256 * 128];              // [n][k] cat(W1_self,W1_neigh)^T
__device__ __half g_W2T[128 * 128];              // [n][k] cat(W2_self,W2_neigh)^T
__device__ float  g_b1 [256];                    // cat(b1, 0)
__device__ float  g_b2 [128];                    // cat(b2, 0)

// ---------------- init: zero CSR state + build fp16 transposed weights ----------------
__global__ void k_init(const float* __restrict__ W1s, const float* __restrict__ W1n,
                       const float* __restrict__ b1,
                       const float* __restrict__ W2s, const float* __restrict__ W2n,
                       const float* __restrict__ b2, int N) {
    int i = blockIdx.x * blockDim.x + threadIdx.x;
    if (i < N) { g_deg[i] = 0; g_cursor[i] = 0; }
    if (i < 256 * 128) {                        // W1T[n][k]
        int n = i >> 7, k = i & 127;
        float v = (n < 128) ? W1s[k * 128 + n] : W1n[k * 128 + (n - 128)];
        g_W1T[i] = __float2half(v);
    }
    int i2 = i - 256 * 128;
    if (i2 >= 0 && i2 < 128 * 128) {            // W2T[n][k]
        int n = i2 >> 7, k = i2 & 127;
        float v = (n < 64) ? W2s[k * 64 + n] : W2n[k * 64 + (n - 64)];
        g_W2T[i2] = __float2half(v);
    }
    if (i < 256) g_b1[i] = (i < 128) ? b1[i] : 0.f;
    if (i < 128) g_b2[i] = (i < 64) ? b2[i] : 0.f;
}

// ---------------- flags + keep-row embedding copy (merged) ----------------
__global__ void k_flagcopy(const float* __restrict__ emb, float* __restrict__ out,
                           const int* __restrict__ keep, int nk,
                           const int* __restrict__ low, int nl) {
    int i = blockIdx.x * blockDim.x + threadIdx.x;
    int nkt = nk * 32;
    if (i < nkt) {
        int r = i >> 5, lane = i & 31;
        int row = keep[r];
        if (lane == 0) g_flag[row] = 1;
        float2 e = *(const float2*)&emb[(size_t)row * 64 + lane * 2];
        *(float2*)&out[(size_t)row * 64 + lane * 2] = e;
    } else {
        int j = i - nkt;
        if (j < nl) g_flag[low[j]] = 2;
    }
}

__global__ void k_degcount(const int* __restrict__ dst, int E) {
    int i = blockIdx.x * blockDim.x + threadIdx.x;
    int base = i * 4;
    if (base + 3 < E) {
        int4 d = *(const int4*)&dst[base];
        atomicAdd(&g_deg[d.x], 1); atomicAdd(&g_deg[d.y], 1);
        atomicAdd(&g_deg[d.z], 1); atomicAdd(&g_deg[d.w], 1);
    } else {
        for (int j = base; j < E; j++) atomicAdd(&g_deg[dst[j]], 1);
    }
}

// ---------------- parallel exclusive scan over degrees (2 kernels) ----------------
__global__ void k_scanA(int N) {
    int i = blockIdx.x * 1024 + threadIdx.x;
    int v = (i < N) ? g_deg[i] : 0;
    #pragma unroll
    for (int o = 16; o; o >>= 1) v += __shfl_down_sync(0xffffffffu, v, o);
    __shared__ int ws[32];
    if ((threadIdx.x & 31) == 0) ws[threadIdx.x >> 5] = v;
    __syncthreads();
    if (threadIdx.x < 32) {
        int s = ws[threadIdx.x];
        #pragma unroll
        for (int o = 16; o; o >>= 1) s += __shfl_down_sync(0xffffffffu, s, o);
        if (threadIdx.x == 0) g_part[blockIdx.x] = s;   // block SUM
    }
}

// scanC: block-local scan + per-block reduction of g_part[0..bid)
__global__ void k_scanC(int N, int E) {
    int i = blockIdx.x * 1024 + threadIdx.x;
    int d = (i < N) ? g_deg[i] : 0;
    int lane = threadIdx.x & 31, w = threadIdx.x >> 5;
    int x = d;
    #pragma unroll
    for (int o = 1; o < 32; o <<= 1) {
        int y = __shfl_up_sync(0xffffffffu, x, o);
        if (lane >= o) x += y;
    }
    __shared__ int ws[32];
    __shared__ int s_pref;
    if (lane == 31) ws[w] = x;
    __syncthreads();
    if (w == 0) {
        int s = ws[lane];
        #pragma unroll
        for (int o = 1; o < 32; o <<= 1) {
            int y = __shfl_up_sync(0xffffffffu, s, o);
            if (lane >= o) s += y;
        }
        ws[lane] = s;
    } else if (w == 1) {
        int p = 0;
        for (int j = lane; j < blockIdx.x; j += 32) p += g_part[j];
        #pragma unroll
        for (int o = 16; o; o >>= 1) p += __shfl_down_sync(0xffffffffu, p, o);
        if (lane == 0) s_pref = p;
    }
    __syncthreads();
    int excl = x - d + (w ? ws[w - 1] : 0) + s_pref;
    if (i < N) {
        g_rowptr[i] = excl;
        g_deginv[i] = 1.0f / (float)((d > 1) ? d : 1);
    }
    if (blockIdx.x == 0 && threadIdx.x == 0) g_rowptr[N] = E;
}

__global__ void k_bin(const int* __restrict__ src, const int* __restrict__ dst, int E) {
    int i = blockIdx.x * blockDim.x + threadIdx.x;
    int base = i * 4;
    if (base + 3 < E) {
        int4 s = *(const int4*)&src[base];
        int4 d = *(const int4*)&dst[base];
        g_esrc[g_rowptr[d.x] + atomicAdd(&g_cursor[d.x], 1)] = s.x;
        g_esrc[g_rowptr[d.y] + atomicAdd(&g_cursor[d.y], 1)] = s.y;
        g_esrc[g_rowptr[d.z] + atomicAdd(&g_cursor[d.z], 1)] = s.z;
        g_esrc[g_rowptr[d.w] + atomicAdd(&g_cursor[d.w], 1)] = s.w;
    } else {
        for (int j = base; j < E; j++) {
            int d = dst[j];
            g_esrc[g_rowptr[d] + atomicAdd(&g_cursor[d], 1)] = src[j];
        }
    }
}

// ---------------- fp16 tensor-core GEMM (m16n8k16, ldmatrix fragments) ----------------
#define AS2 136   // 128 + 8 halves pad; row stride 272B -> ldmatrix conflict-free
#define BS2 136

#define LDSM_X4(r0, r1, r2, r3, addr) \
    asm volatile("ldmatrix.sync.aligned.m8n8.x4.shared.b16 {%0,%1,%2,%3}, [%4];" \
                 : "=r"(r0), "=r"(r1), "=r"(r2), "=r"(r3) : "r"(addr))

template <int NCOLS, bool A_F32>
__global__ void __launch_bounds__(128) k_gemm_h(const float* __restrict__ Xf, int M) {
    __shared__ __half As[64 * AS2];
    __shared__ __half Bs[64 * BS2];
    const __half* WT   = (NCOLS == 256) ? g_W1T : g_W2T;
    const float*  bias = (NCOLS == 256) ? g_b1 : g_b2;

    int bm = blockIdx.x * 64;
    int tid = threadIdx.x;
    int wid = tid >> 5, lane = tid & 31;
    int g = lane >> 2, t = lane & 3;
    int wm = wid >> 1, wn = wid & 1;           // 2x2 warps over 64x64

    uint32_t a_smem = (uint32_t)__cvta_generic_to_shared(As);
    uint32_t b_smem = (uint32_t)__cvta_generic_to_shared(Bs);
    int l7 = lane & 7;
    int a_row_off = ((lane >> 3) & 1) * 8;
    int a_k_off   = ((lane >> 4) & 1) * 8;
    int b_n_off   = ((lane >> 4) & 1) * 8;
    int b_k_off   = ((lane >> 3) & 1) * 8;

    // stage A once (64 rows x 128 halves)
    if (A_F32) {
        #pragma unroll
        for (int i = 0; i < 16; i++) {
            int idx = tid + i * 128;
            int r = idx >> 5, c4 = (idx & 31) << 2;
            int row = bm + r;
            float4 v = (row < M) ? *(const float4*)&Xf[(size_t)row * 128 + c4]
                                 : make_float4(0.f, 0.f, 0.f, 0.f);
            __half2 h0 = __floats2half2_rn(v.x, v.y);
            __half2 h1 = __floats2half2_rn(v.z, v.w);
            uint2 u = make_uint2(*(uint32_t*)&h0, *(uint32_t*)&h1);
            *(uint2*)&As[r * AS2 + c4] = u;
        }
    } else {
        #pragma unroll
        for (int i = 0; i < 16; i++) {
            int idx = tid + i * 128;
            int r = idx >> 5, c4 = (idx & 31) << 2;
            int row = bm + r;
            uint2 u = (row < M) ? *(const uint2*)&g_h1[(size_t)row * 128 + c4]
                                : make_uint2(0u, 0u);
            *(uint2*)&As[r * AS2 + c4] = u;
        }
    }

    for (int bn = 0; bn < NCOLS; bn += 64) {
        __syncthreads();
        #pragma unroll
        for (int i = 0; i < 16; i++) {
            int idx = tid + i * 128;
            int r = idx >> 5, c4 = (idx & 31) << 2;
            uint2 u = *(const uint2*)&WT[(size_t)(bn + r) * 128 + c4];
            *(uint2*)&Bs[r * BS2 + c4] = u;
        }
        __syncthreads();

        float c[2][4][4];
        #pragma unroll
        for (int mt = 0; mt < 2; mt++)
            #pragma unroll
            for (int nt = 0; nt < 4; nt++)
                #pragma unroll
                for (int q = 0; q < 4; q++) c[mt][nt][q] = 0.f;

        #pragma unroll
        for (int k0 = 0; k0 < 128; k0 += 16) {
            uint32_t a[2][4];
            #pragma unroll
            for (int mt = 0; mt < 2; mt++) {
                int arow = wm * 32 + mt * 16 + l7 + a_row_off;
                uint32_t addr = a_smem + (uint32_t)((arow * AS2 + k0 + a_k_off) * 2);
                LDSM_X4(a[mt][0], a[mt][1], a[mt][2], a[mt][3], addr);
            }
            uint32_t b[4][2];
            #pragma unroll
            for (int p = 0; p < 2; p++) {
                int nrow = wn * 32 + p * 16 + l7 + b_n_off;
                uint32_t addr = b_smem + (uint32_t)((nrow * BS2 + k0 + b_k_off) * 2);
                LDSM_X4(b[2 * p][0], b[2 * p][1], b[2 * p + 1][0], b[2 * p + 1][1], addr);
            }
            #pragma unroll
            for (int mt = 0; mt < 2; mt++)
                #pragma unroll
                for (int nt = 0; nt < 4; nt++) {
                    asm volatile(
                        "mma.sync.aligned.m16n8k16.row.col.f32.f16.f16.f32 "
                        "{%0,%1,%2,%3}, {%4,%5,%6,%7}, {%8,%9}, {%0,%1,%2,%3};"
                        : "+f"(c[mt][nt][0]), "+f"(c[mt][nt][1]),
                          "+f"(c[mt][nt][2]), "+f"(c[mt][nt][3])
                        : "r"(a[mt][0]), "r"(a[mt][1]), "r"(a[mt][2]), "r"(a[mt][3]),
                          "r"(b[nt][0]), "r"(b[nt][1]));
                }
        }

        const int HALF = NCOLS / 2;
        #pragma unroll
        for (int mt = 0; mt < 2; mt++) {
            int row = bm + wm * 32 + mt * 16 + g;
            #pragma unroll
            for (int nt = 0; nt < 4; nt++) {
                int col = bn + wn * 32 + nt * 8 + 2 * t;
                float bx = bias[col], by = bias[col + 1];
                __half2 o0 = __floats2half2_rn(c[mt][nt][0] + bx, c[mt][nt][1] + by);
                __half2 o1 = __floats2half2_rn(c[mt][nt][2] + bx, c[mt][nt][3] + by);
                __half* dstS = (NCOLS == 256) ? g_X1s : g_Ys;
                __half* dstN = (NCOLS == 256) ? g_X1n : g_Yn;
                if (col < HALF) {
                    if (row < M)     *(__half2*)&dstS[(size_t)row * HALF + col] = o0;
                    if (row + 8 < M) *(__half2*)&dstS[(size_t)(row + 8) * HALF + col] = o1;
                } else {
                    int cn = col - HALF;
                    if (row < M)     *(__half2*)&dstN[(size_t)row * HALF + cn] = o0;
                    if (row + 8 < M) *(__half2*)&dstN[(size_t)(row + 8) * HALF + cn] = o1;
                }
            }
        }
    }
}

// ---------------- layer-1 aggregation: warp per node, 2 edges/warp (uint4) ----------------
__global__ void k_agg1(int N) {
    int w = (blockIdx.x * blockDim.x + threadIdx.x) >> 5;
    int lane = threadIdx.x & 31;
    if (w >= N) return;
    int half = lane >> 4;        // 0 or 1
    int hl   = lane & 15;        // channel group: halves [hl*8, hl*8+8)
    int beg = g_rowptr[w], end = g_rowptr[w + 1];
    const uint4* Xn = (const uint4*)g_X1n;   // row = 16 uint4

    float acc[8];
    #pragma unroll
    for (int q = 0; q < 8; q++) acc[q] = 0.f;

    int j = beg + half;
    for (; j + 6 < end; j += 8) {            // 4 edges per half per iter
        int s0 = g_esrc[j],     s1 = g_esrc[j + 2];
        int s2 = g_esrc[j + 4], s3 = g_esrc[j + 6];
        uint4 u0 = Xn[(size_t)s0 * 16 + hl];
        uint4 u1 = Xn[(size_t)s1 * 16 + hl];
        uint4 u2 = Xn[(size_t)s2 * 16 + hl];
        uint4 u3 = Xn[(size_t)s3 * 16 + hl];
        const uint32_t* uu[4] = {&u0.x, &u1.x, &u2.x, &u3.x};
        #pragma unroll
        for (int e = 0; e < 4; e++) {
            #pragma unroll
            for (int q = 0; q < 4; q++) {
                float2 v = __half22float2(*(const __half2*)&uu[e][q]);
                acc[2 * q]     += v.x;
                acc[2 * q + 1] += v.y;
            }
        }
    }
    for (; j < end; j += 2) {
        uint4 u0 = Xn[(size_t)g_esrc[j] * 16 + hl];
        const uint32_t* uu = &u0.x;
        #pragma unroll
        for (int q = 0; q < 4; q++) {
            float2 v = __half22float2(*(const __half2*)&uu[q]);
            acc[2 * q]     += v.x;
            acc[2 * q + 1] += v.y;
        }
    }
    // merge even/odd halves
    #pragma unroll
    for (int q = 0; q < 8; q++) acc[q] += __shfl_xor_sync(0xffffffffu, acc[q], 16);

    if (half == 0) {
        float di = g_deginv[w];
        uint4 us = *(const uint4*)&g_X1s[(size_t)w * 128 + hl * 8];
        const uint32_t* su = &us.x;
        uint4 uo;
        uint32_t* ou = &uo.x;
        #pragma unroll
        for (int q = 0; q < 4; q++) {
            float2 s = __half22float2(*(const __half2*)&su[q]);
            float hx = fmaxf(fmaf(acc[2 * q],     di, s.x), 0.f);
            float hy = fmaxf(fmaf(acc[2 * q + 1], di, s.y), 0.f);
            __half2 h = __floats2half2_rn(hx, hy);
            ou[q] = *(uint32_t*)&h;
        }
        *(uint4*)&g_h1[(size_t)w * 128 + hl * 8] = uo;
    }
}

// ---------------- layer-2 aggregation + final: 4 edges/warp (uint4) ----------------
// Octet o (lane>>3) handles edges beg+o, beg+o+4, ...; 8 lanes x uint4 cover a 128B
// Yn row. Quarters merged with shfl_xor(8) + shfl_xor(16); octet 0 writes output.
__global__ void k_final(const float* __restrict__ emb, float* __restrict__ out, int N) {
    int w = (blockIdx.x * blockDim.x + threadIdx.x) >> 5;
    int lane = threadIdx.x & 31;
    if (w >= N) return;
    unsigned char f = g_flag[w];
    if (f == 1) return;                       // already written by k_flagcopy
    int q4 = lane >> 3;          // 0..3
    int hl = lane & 7;           // channel group: halves [hl*8, hl*8+8)
    int beg = g_rowptr[w], end = g_rowptr[w + 1];
    const uint4* Yn = (const uint4*)g_Yn;    // row = 8 uint4

    float acc[8];
    #pragma unroll
    for (int q = 0; q < 8; q++) acc[q] = 0.f;

    int j = beg + q4;
    for (; j + 12 < end; j += 16) {          // 4 edges per octet per iter
        int s0 = g_esrc[j],     s1 = g_esrc[j + 4];
        int s2 = g_esrc[j + 8], s3 = g_esrc[j + 12];
        uint4 u0 = Yn[(size_t)s0 * 8 + hl];
        uint4 u1 = Yn[(size_t)s1 * 8 + hl];
        uint4 u2 = Yn[(size_t)s2 * 8 + hl];
        uint4 u3 = Yn[(size_t)s3 * 8 + hl];
        const uint32_t* uu[4] = {&u0.x, &u1.x, &u2.x, &u3.x};
        #pragma unroll
        for (int e = 0; e < 4; e++) {
            #pragma unroll
            for (int q = 0; q < 4; q++) {
                float2 v = __half22float2(*(const __half2*)&uu[e][q]);
                acc[2 * q]     += v.x;
                acc[2 * q + 1] += v.y;
            }
        }
    }
    for (; j < end; j += 4) {
        uint4 u0 = Yn[(size_t)g_esrc[j] * 8 + hl];
        const uint32_t* uu = &u0.x;
        #pragma unroll
        for (int q = 0; q < 4; q++) {
            float2 v = __half22float2(*(const __half2*)&uu[q]);
            acc[2 * q]     += v.x;
            acc[2 * q + 1] += v.y;
        }
    }
    // merge the four octets
    #pragma unroll
    for (int q = 0; q < 8; q++) {
        acc[q] += __shfl_xor_sync(0xffffffffu, acc[q], 8);
        acc[q] += __shfl_xor_sync(0xffffffffu, acc[q], 16);
    }

    if (q4 == 0) {
        float di = g_deginv[w];
        uint4 us = *(const uint4*)&g_Ys[(size_t)w * 64 + hl * 8];
        const uint32_t* su = &us.x;
        float sc = (f == 2) ? 2.f : 1.f;
        float ov[8];
        #pragma unroll
        for (int q = 0; q < 4; q++) {
            float2 s = __half22float2(*(const __half2*)&su[q]);
            ov[2 * q]     = (s.x + acc[2 * q]     * di) * sc;
            ov[2 * q + 1] = (s.y + acc[2 * q + 1] * di) * sc;
        }
        float4 o0 = make_float4(ov[0], ov[1], ov[2], ov[3]);
        float4 o1 = make_float4(ov[4], ov[5], ov[6], ov[7]);
        *(float4*)&out[(size_t)w * 64 + hl * 8]     = o0;
        *(float4*)&out[(size_t)w * 64 + hl * 8 + 4] = o1;
    }
}

// ---------------- launch ----------------
extern "C" void kernel_launch(void* const* d_in, const int* in_sizes, int n_in,
                              void* d_out, int out_size) {
    const float* features = (const float*)d_in[0];
    const float* W1s = (const float*)d_in[1];
    const float* W1n = (const float*)d_in[2];
    const float* b1  = (const float*)d_in[3];
    const float* W2s = (const float*)d_in[4];
    const float* W2n = (const float*)d_in[5];
    const float* b2  = (const float*)d_in[6];
    const float* emb = (const float*)d_in[7];
    const int* src   = (const int*)d_in[8];
    const int* dst   = (const int*)d_in[9];
    const int* keep  = (const int*)d_in[10];
    const int* low   = (const int*)d_in[11];

    int N  = in_sizes[0] / 128;
    int E  = in_sizes[8];
    int nk = in_sizes[10];
    int nl = in_sizes[11];
    float* out = (float*)d_out;

    static cudaStream_t s2 = nullptr;
    static cudaEvent_t ev_fork = nullptr, ev_join = nullptr;
    if (!s2) {
        cudaStreamCreateWithFlags(&s2, cudaStreamNonBlocking);
        cudaEventCreateWithFlags(&ev_fork, cudaEventDisableTiming);
        cudaEventCreateWithFlags(&ev_join, cudaEventDisableTiming);
    }

    int nb = (N + 1023) / 1024;   // scan blocks (<=128)

    // stream 0: init, then fork CSR build onto s2
    k_init<<<(N + 255) / 256, 256>>>(W1s, W1n, b1, W2s, W2n, b2, N);
    cudaEventRecord(ev_fork, 0);
    cudaStreamWaitEvent(s2, ev_fork, 0);

    // s2: CSR build chain (independent of GEMM1)
    k_degcount<<<(E / 4 + 255) / 256, 256, 0, s2>>>(dst, E);
    k_scanA<<<nb, 1024, 0, s2>>>(N);
    k_scanC<<<nb, 1024, 0, s2>>>(N, E);
    k_bin<<<(E / 4 + 255) / 256, 256, 0, s2>>>(src, dst, E);
    cudaEventRecord(ev_join, s2);

    // stream 0 meanwhile: GEMM1, flags+keepcopy
    k_gemm_h<256, true><<<(N + 63) / 64, 128>>>(features, N);
    k_flagcopy<<<(nk * 32 + nl + 255) / 256, 256>>>(emb, out, keep, nk, low, nl);

    // join: aggregation needs CSR + layer-1 GEMM
    cudaStreamWaitEvent(0, ev_join, 0);
    k_agg1<<<(N + 7) / 8, 256>>>(N);
    k_gemm_h<128, false><<<(N + 63) / 64, 128>>>(nullptr, N);
    k_final<<<(N + 7) / 8, 256>>>(emb, out, N);
}